// round 3
// baseline (speedup 1.0000x reference)
#include <cuda_runtime.h>

// VecInt: scaling-and-squaring integration of a stationary velocity field.
// vec (1,3,160,192,160) fp32, nsteps=7.
//
// Round 3: duplicated-x line layout. Each 128B line holds 8 float4 voxels
// covering x in [7k, 7k+7] (x=7k+7 duplicated as slot 0 of the next line).
// Every trilinear x-pair (x0, x0+1) is then guaranteed to live in ONE 128B
// line, eliminating the 1/8 line-crossing penalty: gather cost drops from
// 4.5 to exactly 4.0 L1 wavefronts per voxel. Swizzled x-offset = x + x/7.
// Pair-lane scheme retained: even lane takes x0, odd lane takes x1; border
// handling via per-lane weight select (exact border-zero semantics).

constexpr int D = 160;
constexpr int H = 192;
constexpr int W = 160;
constexpr int NVOX = D * H * W;            // 4,915,200
constexpr int NSTEPS = 7;

constexpr int LINESX  = 23;                // ceil(159/7) lines per x-row
constexpr int XSTRIDE = LINESX * 8;        // 184 float4 per x-row
constexpr int NELEM   = D * H * XSTRIDE;   // 5,652,480

__device__ __align__(128) float4 g_bufA[NELEM];
__device__ __align__(128) float4 g_bufB[NELEM];

__device__ __forceinline__ int div7(int x) {
    // exact floor(x/7) for 0 <= x <= 1871
    return (x * 9363) >> 16;
}

__global__ void __launch_bounds__(256)
scale_in_kernel(const float* __restrict__ in, float4* __restrict__ out)
{
    int idx = blockIdx.x * 256 + threadIdx.x;   // canonical voxel id
    int x = idx % W;
    int t = idx / W;
    int y = t % H;
    int z = t / H;

    const float s = 1.0f / 128.0f;   // 1/2^7
    float4 r;
    r.x = in[idx]            * (s * 0.5f * (D - 1));
    r.y = in[idx + NVOX]     * (s * 0.5f * (H - 1));
    r.z = in[idx + 2 * NVOX] * (s * 0.5f * (W - 1));
    r.w = 0.0f;

    int k    = div7(x);
    int xoff = x + k;                       // 8k + (x - 7k)
    int off  = (z * H + y) * XSTRIDE + xoff;
    out[off] = r;
    // duplicate: x = 7k (k>0) also lives at slot 7 of line k-1 == off-1
    if ((x - 7 * k) == 0 && k > 0)
        out[off - 1] = r;
}

// 2 lanes per voxel. sub==0 lane handles x-pair slot +0, sub==1 slot +1.
template<bool LAST>
__global__ void __launch_bounds__(256)
integrate_kernel(const float4* __restrict__ in, float4* __restrict__ out4,
                 float* __restrict__ out_soa)
{
    int t   = blockIdx.x * 256 + threadIdx.x;
    int idx = t >> 1;
    int sub = t & 1;

    int x  = idx % W;
    int tt = idx / W;
    int y  = tt % H;
    int z  = tt / H;

    int kself   = div7(x);
    int rowself = (z * H + y) * XSTRIDE;
    float4 v = in[rowself + x + kself];     // broadcast across pair lanes

    float zf = (float)z + v.x;
    float yf = (float)y + v.y;
    float xf = (float)x + v.z;

    float z0f = floorf(zf), y0f = floorf(yf), x0f = floorf(xf);
    float fz = zf - z0f, fy = yf - y0f, fx = xf - x0f;
    int z0 = (int)z0f, y0 = (int)y0f, x0 = (int)x0f;
    int z1 = z0 + 1, y1 = y0 + 1;

    // y/z: validity folded into weights, clamped safe indices
    float Wz0 = ((unsigned)z0 < (unsigned)D) ? (1.0f - fz) : 0.0f;
    float Wz1 = ((unsigned)z1 < (unsigned)D) ? fz          : 0.0f;
    float Wy0 = ((unsigned)y0 < (unsigned)H) ? (1.0f - fy) : 0.0f;
    float Wy1 = ((unsigned)y1 < (unsigned)H) ? fy          : 0.0f;

    int zc0 = min(max(z0, 0), D - 1), zc1 = min(max(z1, 0), D - 1);
    int yc0 = min(max(y0, 0), H - 1), yc1 = min(max(y1, 0), H - 1);

    // x: pair base clamped into [0, W-2]; this lane's sampled column
    int   b   = min(max(x0, 0), W - 2);
    int   pos = b + sub;
    // per-lane x weight with exact border-zero semantics
    float wx  = (pos == x0) ? (1.0f - fx) : ((pos == x0 + 1) ? fx : 0.0f);

    int xoffL = pos + div7(b);              // guaranteed same line for both lanes

    int r00 = (zc0 * H + yc0) * XSTRIDE + xoffL;
    int r01 = (zc0 * H + yc1) * XSTRIDE + xoffL;
    int r10 = (zc1 * H + yc0) * XSTRIDE + xoffL;
    int r11 = (zc1 * H + yc1) * XSTRIDE + xoffL;

    float4 c00 = in[r00];
    float4 c01 = in[r01];
    float4 c10 = in[r10];
    float4 c11 = in[r11];

    float px, py, pz;
    {
        float a0 = fmaf(c01.x, Wy1, c00.x * Wy0);
        float a1 = fmaf(c11.x, Wy1, c10.x * Wy0);
        px = wx * fmaf(a1, Wz1, a0 * Wz0);
    }
    {
        float a0 = fmaf(c01.y, Wy1, c00.y * Wy0);
        float a1 = fmaf(c11.y, Wy1, c10.y * Wy0);
        py = wx * fmaf(a1, Wz1, a0 * Wz0);
    }
    {
        float a0 = fmaf(c01.z, Wy1, c00.z * Wy0);
        float a1 = fmaf(c11.z, Wy1, c10.z * Wy0);
        pz = wx * fmaf(a1, Wz1, a0 * Wz0);
    }
    px += __shfl_xor_sync(0xFFFFFFFFu, px, 1);
    py += __shfl_xor_sync(0xFFFFFFFFu, py, 1);
    pz += __shfl_xor_sync(0xFFFFFFFFu, pz, 1);

    if (!LAST) {
        float4 r;
        r.x = v.x + px;
        r.y = v.y + py;
        r.z = v.z + pz;
        r.w = 0.0f;
        int off = rowself + x + kself;
        if (sub == 0) {
            out4[off] = r;
        } else {
            // odd lane maintains the duplicate slot (x = 7k, k > 0)
            if ((x - 7 * kself) == 0 && kself > 0)
                out4[off - 1] = r;
        }
    } else {
        if (sub == 0) {
            out_soa[idx]            = (v.x + px) * (1.0f / (0.5f * (D - 1)));
            out_soa[idx + NVOX]     = (v.y + py) * (1.0f / (0.5f * (H - 1)));
            out_soa[idx + 2 * NVOX] = (v.z + pz) * (1.0f / (0.5f * (W - 1)));
        }
    }
}

extern "C" void kernel_launch(void* const* d_in, const int* in_sizes, int n_in,
                              void* d_out, int out_size)
{
    const float* vec = (const float*)d_in[0];
    float* out = (float*)d_out;

    float4 *bufA, *bufB;
    cudaGetSymbolAddress((void**)&bufA, g_bufA);
    cudaGetSymbolAddress((void**)&bufB, g_bufB);

    const int threads = 256;
    const int blocks_scale = NVOX / threads;          // 19200
    const int blocks_int   = (2 * NVOX) / threads;    // 38400

    scale_in_kernel<<<blocks_scale, threads>>>(vec, bufA);

    float4* cur = bufA;
    float4* nxt = bufB;
    for (int i = 0; i < NSTEPS - 1; ++i) {
        integrate_kernel<false><<<blocks_int, threads>>>(cur, nxt, nullptr);
        float4* tmp = cur; cur = nxt; nxt = tmp;
    }
    integrate_kernel<true><<<blocks_int, threads>>>(cur, nullptr, out);
}

// round 4
// speedup vs baseline: 1.0424x; 1.0424x over previous
#include <cuda_runtime.h>

// VecInt: scaling-and-squaring integration of a stationary velocity field.
// vec (1,3,160,192,160) fp32, nsteps=7.
//
// Round 4: revert to R2 pair-lane layout (best so far) + streaming-optimal
// SoA->AoS ingest (4 voxels/thread, vector loads/stores) + ALU trims
// (__float2int_rd floors). Pair-lane gather: even lane takes x0 column,
// odd lane takes x1; the x-adjacent 32B corner pair lands in one load
// instruction at adjacent lanes -> single L1 wavefront most of the time.

constexpr int D = 160;
constexpr int H = 192;
constexpr int W = 160;
constexpr int NVOX = D * H * W;          // 4,915,200 (divisible by 1024)
constexpr int NSTEPS = 7;

__device__ __align__(128) float4 g_bufA[NVOX];
__device__ __align__(128) float4 g_bufB[NVOX];

__global__ void __launch_bounds__(256)
scale_in_kernel(const float* __restrict__ in, float4* __restrict__ out)
{
    int i4 = blockIdx.x * 256 + threadIdx.x;   // handles voxels 4*i4 .. 4*i4+3
    const float s  = 1.0f / 128.0f;            // 1/2^7
    const float sx = s * 0.5f * (D - 1);
    const float sy = s * 0.5f * (H - 1);
    const float sz = s * 0.5f * (W - 1);

    float4 a = reinterpret_cast<const float4*>(in)[i4];              // ch z
    float4 b = reinterpret_cast<const float4*>(in + NVOX)[i4];      // ch y
    float4 c = reinterpret_cast<const float4*>(in + 2 * NVOX)[i4];  // ch x

    int base = i4 * 4;
    out[base + 0] = make_float4(a.x * sx, b.x * sy, c.x * sz, 0.0f);
    out[base + 1] = make_float4(a.y * sx, b.y * sy, c.y * sz, 0.0f);
    out[base + 2] = make_float4(a.z * sx, b.z * sy, c.z * sz, 0.0f);
    out[base + 3] = make_float4(a.w * sx, b.w * sy, c.w * sz, 0.0f);
}

// 2 lanes per voxel. sub==0 lane handles x0 corners, sub==1 lane handles x1.
template<bool LAST>
__global__ void __launch_bounds__(256)
integrate_kernel(const float4* __restrict__ in, float4* __restrict__ out4,
                 float* __restrict__ out_soa)
{
    int t   = blockIdx.x * 256 + threadIdx.x;
    int idx = t >> 1;
    int sub = t & 1;

    int x  = idx % W;
    int tt = idx / W;
    int y  = tt % H;
    int z  = tt / H;

    float4 v = in[idx];   // same address in both pair lanes -> broadcast

    float zf = (float)z + v.x;
    float yf = (float)y + v.y;
    float xf = (float)x + v.z;

    int z0 = __float2int_rd(zf);
    int y0 = __float2int_rd(yf);
    int x0 = __float2int_rd(xf);
    float fz = zf - (float)z0;
    float fy = yf - (float)y0;
    float fx = xf - (float)x0;
    int z1 = z0 + 1, y1 = y0 + 1;

    // validity folded into weights (border-zero semantics)
    float Wz0 = ((unsigned)z0 < (unsigned)D) ? (1.0f - fz) : 0.0f;
    float Wz1 = ((unsigned)z1 < (unsigned)D) ? fz          : 0.0f;
    float Wy0 = ((unsigned)y0 < (unsigned)H) ? (1.0f - fy) : 0.0f;
    float Wy1 = ((unsigned)y1 < (unsigned)H) ? fy          : 0.0f;
    float Wx0 = ((unsigned)x0 < (unsigned)W) ? (1.0f - fx) : 0.0f;
    float Wx1 = ((unsigned)(x0 + 1) < (unsigned)W) ? fx    : 0.0f;

    int zc0 = min(max(z0, 0), D - 1), zc1 = min(max(z1, 0), D - 1);
    int yc0 = min(max(y0, 0), H - 1), yc1 = min(max(y1, 0), H - 1);
    int xc0 = min(max(x0, 0), W - 1), xc1 = min(max(x0 + 1, 0), W - 1);

    // this lane's x column + x weight
    int   xc = sub ? xc1 : xc0;
    float wx = sub ? Wx1 : Wx0;

    int r00 = (zc0 * H + yc0) * W + xc;   // (z0,y0)
    int r01 = (zc0 * H + yc1) * W + xc;   // (z0,y1)
    int r10 = (zc1 * H + yc0) * W + xc;   // (z1,y0)
    int r11 = (zc1 * H + yc1) * W + xc;   // (z1,y1)

    // 4 corner gathers; pair lanes hit adjacent float4s -> shared wavefront
    float4 c00 = in[r00];
    float4 c01 = in[r01];
    float4 c10 = in[r10];
    float4 c11 = in[r11];

    float px, py, pz;
    {
        float a0 = fmaf(c01.x, Wy1, c00.x * Wy0);
        float a1 = fmaf(c11.x, Wy1, c10.x * Wy0);
        px = wx * fmaf(a1, Wz1, a0 * Wz0);
    }
    {
        float a0 = fmaf(c01.y, Wy1, c00.y * Wy0);
        float a1 = fmaf(c11.y, Wy1, c10.y * Wy0);
        py = wx * fmaf(a1, Wz1, a0 * Wz0);
    }
    {
        float a0 = fmaf(c01.z, Wy1, c00.z * Wy0);
        float a1 = fmaf(c11.z, Wy1, c10.z * Wy0);
        pz = wx * fmaf(a1, Wz1, a0 * Wz0);
    }
    px += __shfl_xor_sync(0xFFFFFFFFu, px, 1);
    py += __shfl_xor_sync(0xFFFFFFFFu, py, 1);
    pz += __shfl_xor_sync(0xFFFFFFFFu, pz, 1);

    if (sub == 0) {
        if (!LAST) {
            float4 r;
            r.x = v.x + px;
            r.y = v.y + py;
            r.z = v.z + pz;
            r.w = 0.0f;
            out4[idx] = r;
        } else {
            out_soa[idx]            = (v.x + px) * (1.0f / (0.5f * (D - 1)));
            out_soa[idx + NVOX]     = (v.y + py) * (1.0f / (0.5f * (H - 1)));
            out_soa[idx + 2 * NVOX] = (v.z + pz) * (1.0f / (0.5f * (W - 1)));
        }
    }
}

extern "C" void kernel_launch(void* const* d_in, const int* in_sizes, int n_in,
                              void* d_out, int out_size)
{
    const float* vec = (const float*)d_in[0];
    float* out = (float*)d_out;

    float4 *bufA, *bufB;
    cudaGetSymbolAddress((void**)&bufA, g_bufA);
    cudaGetSymbolAddress((void**)&bufB, g_bufB);

    const int threads = 256;
    const int blocks_scale = NVOX / (threads * 4);    // 4800
    const int blocks_int   = (2 * NVOX) / threads;    // 38400

    scale_in_kernel<<<blocks_scale, threads>>>(vec, bufA);

    float4* cur = bufA;
    float4* nxt = bufB;
    for (int i = 0; i < NSTEPS - 1; ++i) {
        integrate_kernel<false><<<blocks_int, threads>>>(cur, nxt, nullptr);
        float4* tmp = cur; cur = nxt; nxt = tmp;
    }
    integrate_kernel<true><<<blocks_int, threads>>>(cur, nullptr, out);
}

// round 5
// speedup vs baseline: 1.0518x; 1.0091x over previous
#include <cuda_runtime.h>

// VecInt: scaling-and-squaring integration of a stationary velocity field.
// vec (1,3,160,192,160) fp32, nsteps=7.
//
// Round 5: R4 memory scheme (pair-lane x-gather, AoS float4 ping-pong) with
// decode trims: 2D grid — blockIdx.x = y, blockIdx.y = z, one x-row per
// 320-thread block (2 lanes/voxel * 160) — removes all per-thread div/mod.
// Arithmetic identical to R4 (same rel_err). L1tex wavefronts are the
// binding resource (~4.75/voxel, measured at roofline); this round only
// removes issue overhead.

constexpr int D = 160;
constexpr int H = 192;
constexpr int W = 160;
constexpr int NVOX = D * H * W;          // 4,915,200
constexpr int NSTEPS = 7;

__device__ __align__(128) float4 g_bufA[NVOX];
__device__ __align__(128) float4 g_bufB[NVOX];

__global__ void __launch_bounds__(256)
scale_in_kernel(const float* __restrict__ in, float4* __restrict__ out)
{
    int i4 = blockIdx.x * 256 + threadIdx.x;   // handles voxels 4*i4 .. 4*i4+3
    const float s  = 1.0f / 128.0f;            // 1/2^7
    const float sx = s * 0.5f * (D - 1);
    const float sy = s * 0.5f * (H - 1);
    const float sz = s * 0.5f * (W - 1);

    float4 a = reinterpret_cast<const float4*>(in)[i4];             // ch z
    float4 b = reinterpret_cast<const float4*>(in + NVOX)[i4];      // ch y
    float4 c = reinterpret_cast<const float4*>(in + 2 * NVOX)[i4];  // ch x

    int base = i4 * 4;
    out[base + 0] = make_float4(a.x * sx, b.x * sy, c.x * sz, 0.0f);
    out[base + 1] = make_float4(a.y * sx, b.y * sy, c.y * sz, 0.0f);
    out[base + 2] = make_float4(a.z * sx, b.z * sy, c.z * sz, 0.0f);
    out[base + 3] = make_float4(a.w * sx, b.w * sy, c.w * sz, 0.0f);
}

// One x-row per block: blockIdx.x = y, blockIdx.y = z, 320 threads = 160
// voxels * 2 lanes. sub==0 lane handles x0 corners, sub==1 handles x1.
template<bool LAST>
__global__ void __launch_bounds__(320)
integrate_kernel(const float4* __restrict__ in, float4* __restrict__ out4,
                 float* __restrict__ out_soa)
{
    int x   = threadIdx.x >> 1;
    int sub = threadIdx.x & 1;
    int y   = blockIdx.x;
    int z   = blockIdx.y;
    int idx = (z * H + y) * W + x;

    float4 v = in[idx];   // same address in both pair lanes -> broadcast

    float zf = (float)z + v.x;
    float yf = (float)y + v.y;
    float xf = (float)x + v.z;

    int z0 = __float2int_rd(zf);
    int y0 = __float2int_rd(yf);
    int x0 = __float2int_rd(xf);
    float fz = zf - (float)z0;
    float fy = yf - (float)y0;
    float fx = xf - (float)x0;
    int z1 = z0 + 1, y1 = y0 + 1;

    // validity folded into weights (border-zero semantics)
    float Wz0 = ((unsigned)z0 < (unsigned)D) ? (1.0f - fz) : 0.0f;
    float Wz1 = ((unsigned)z1 < (unsigned)D) ? fz          : 0.0f;
    float Wy0 = ((unsigned)y0 < (unsigned)H) ? (1.0f - fy) : 0.0f;
    float Wy1 = ((unsigned)y1 < (unsigned)H) ? fy          : 0.0f;
    float Wx0 = ((unsigned)x0 < (unsigned)W) ? (1.0f - fx) : 0.0f;
    float Wx1 = ((unsigned)(x0 + 1) < (unsigned)W) ? fx    : 0.0f;

    int zc0 = min(max(z0, 0), D - 1), zc1 = min(max(z1, 0), D - 1);
    int yc0 = min(max(y0, 0), H - 1), yc1 = min(max(y1, 0), H - 1);
    int xc0 = min(max(x0, 0), W - 1), xc1 = min(max(x0 + 1, 0), W - 1);

    // this lane's x column + x weight
    int   xc = sub ? xc1 : xc0;
    float wx = sub ? Wx1 : Wx0;

    int r00 = (zc0 * H + yc0) * W + xc;   // (z0,y0)
    int r01 = (zc0 * H + yc1) * W + xc;   // (z0,y1)
    int r10 = (zc1 * H + yc0) * W + xc;   // (z1,y0)
    int r11 = (zc1 * H + yc1) * W + xc;   // (z1,y1)

    // 4 corner gathers; pair lanes hit adjacent float4s -> shared wavefront
    float4 c00 = in[r00];
    float4 c01 = in[r01];
    float4 c10 = in[r10];
    float4 c11 = in[r11];

    float px, py, pz;
    {
        float a0 = fmaf(c01.x, Wy1, c00.x * Wy0);
        float a1 = fmaf(c11.x, Wy1, c10.x * Wy0);
        px = wx * fmaf(a1, Wz1, a0 * Wz0);
    }
    {
        float a0 = fmaf(c01.y, Wy1, c00.y * Wy0);
        float a1 = fmaf(c11.y, Wy1, c10.y * Wy0);
        py = wx * fmaf(a1, Wz1, a0 * Wz0);
    }
    {
        float a0 = fmaf(c01.z, Wy1, c00.z * Wy0);
        float a1 = fmaf(c11.z, Wy1, c10.z * Wy0);
        pz = wx * fmaf(a1, Wz1, a0 * Wz0);
    }
    px += __shfl_xor_sync(0xFFFFFFFFu, px, 1);
    py += __shfl_xor_sync(0xFFFFFFFFu, py, 1);
    pz += __shfl_xor_sync(0xFFFFFFFFu, pz, 1);

    if (sub == 0) {
        if (!LAST) {
            float4 r;
            r.x = v.x + px;
            r.y = v.y + py;
            r.z = v.z + pz;
            r.w = 0.0f;
            out4[idx] = r;
        } else {
            out_soa[idx]            = (v.x + px) * (1.0f / (0.5f * (D - 1)));
            out_soa[idx + NVOX]     = (v.y + py) * (1.0f / (0.5f * (H - 1)));
            out_soa[idx + 2 * NVOX] = (v.z + pz) * (1.0f / (0.5f * (W - 1)));
        }
    }
}

extern "C" void kernel_launch(void* const* d_in, const int* in_sizes, int n_in,
                              void* d_out, int out_size)
{
    const float* vec = (const float*)d_in[0];
    float* out = (float*)d_out;

    float4 *bufA, *bufB;
    cudaGetSymbolAddress((void**)&bufA, g_bufA);
    cudaGetSymbolAddress((void**)&bufB, g_bufB);

    const int blocks_scale = NVOX / (256 * 4);    // 4800
    dim3 grid_int(H, D);                          // y, z
    const int threads_int = 2 * W;                // 320

    scale_in_kernel<<<blocks_scale, 256>>>(vec, bufA);

    float4* cur = bufA;
    float4* nxt = bufB;
    for (int i = 0; i < NSTEPS - 1; ++i) {
        integrate_kernel<false><<<grid_int, threads_int>>>(cur, nxt, nullptr);
        float4* tmp = cur; cur = nxt; nxt = tmp;
    }
    integrate_kernel<true><<<grid_int, threads_int>>>(cur, nullptr, out);
}